// round 5
// baseline (speedup 1.0000x reference)
#include <cuda_runtime.h>
#include <cuda_fp16.h>
#include <cstdint>

#define TD 256
#define TILE_M 128
#define NTHREADS 256

// ---- w2 half image: 256 k-rows x 272B (16B-aligned, 272/16=17 -> conflict-free) ----
#define W2H_STRIDE 272
#define W2H_BYTES  (256 * W2H_STRIDE)        // 69632 per half
#define W1_STRIDE  528
#define OFF_TAIL   (2 * W2H_BYTES)           // shared tail: w1 + b1f + b2
#define TAIL_W1    0
#define TAIL_B1F   (16 * W1_STRIDE)          // 8448
#define TAIL_B2    (TAIL_B1F + 1024)         // 9472
#define TAIL_BYTES (TAIL_B2 + 1024)          // 10496
#define IMG_BYTES  (OFF_TAIL + TAIL_BYTES)   // 149760

// ---- per-CTA smem layout ----
#define S_W2   0
#define S_W1   W2H_BYTES                     // 69632
#define S_B1F  (S_W1 + 16 * W1_STRIDE)       // 78080
#define S_B2   (S_B1F + 1024)                // 79104
#define S_ST   (S_B2 + 1024)                 // 80128
#define ST_STRIDE 48
#define SMEM_DYN (S_ST + TILE_M * ST_STRIDE) // 86272  -> 2 CTAs/SM

__device__ __align__(16) unsigned char g_img[IMG_BYTES];

// ============================ helpers ============================
__device__ __forceinline__ uint32_t smem_u32(const void* p) {
    uint32_t a;
    asm("{ .reg .u64 t; cvta.to.shared.u64 t, %1; cvt.u32.u64 %0, t; }"
        : "=r"(a) : "l"(p));
    return a;
}

#define LDSM_X4(r0, r1, r2, r3, addr) \
    asm volatile("ldmatrix.sync.aligned.m8n8.x4.shared.b16 {%0,%1,%2,%3}, [%4];" \
        : "=r"(r0), "=r"(r1), "=r"(r2), "=r"(r3) : "r"(addr))

#define LDSM_X4_T(r0, r1, r2, r3, addr) \
    asm volatile("ldmatrix.sync.aligned.m8n8.x4.trans.shared.b16 {%0,%1,%2,%3}, [%4];" \
        : "=r"(r0), "=r"(r1), "=r"(r2), "=r"(r3) : "r"(addr))

// D += A @ B : m16n8k16, fp16 in, fp32 accumulate
#define MMA16816(c, a0, a1, a2, a3, b0, b1) \
    asm volatile("mma.sync.aligned.m16n8k16.row.col.f32.f16.f16.f32 " \
        "{%0,%1,%2,%3}, {%4,%5,%6,%7}, {%8,%9}, {%0,%1,%2,%3};" \
        : "+f"((c)[0]), "+f"((c)[1]), "+f"((c)[2]), "+f"((c)[3]) \
        : "r"(a0), "r"(a1), "r"(a2), "r"(a3), "r"(b0), "r"(b1))

#define CP_ASYNC16(dst, src) \
    asm volatile("cp.async.ca.shared.global [%0], [%1], 16;" \
        :: "r"(dst), "l"(src) : "memory")

__device__ __forceinline__ float fast_gelu(float x) {
    float t = 0.7978845608f * x * fmaf(0.044715f, x * x, 1.0f);
    float th;
    asm("tanh.approx.f32 %0, %1;" : "=f"(th) : "f"(t));
    return 0.5f * x * (1.0f + th);
}

// ============================ prep kernel ============================
// Blocks 0..255: w2 row k -> both half-images (n>>7 selects half, n&127 local col).
// Block 256: w1 rows (zero-padded k=16) + folded fp32 bias + b2 into shared tail.
__global__ void prep_kernel(const float* __restrict__ w1, const float* __restrict__ b1,
                            const float* __restrict__ w2, const float* __restrict__ b2) {
    const int n = threadIdx.x;
    const int blk = blockIdx.x;
    if (blk < 256) {
        *(__half*)(g_img + (n >> 7) * W2H_BYTES + blk * W2H_STRIDE + (n & 127) * 2)
            = __float2half_rn(w2[blk * TD + n]);
    } else {
        #pragma unroll
        for (int k = 0; k < 16; k++) {
            float v = (k < 14) ? w1[k * TD + n] : 0.0f;
            *(__half*)(g_img + OFF_TAIL + TAIL_W1 + k * W1_STRIDE + n * 2) = __float2half_rn(v);
        }
        ((float*)(g_img + OFF_TAIL + TAIL_B1F))[n] = b1[n] + 128.0f * w1[12 * TD + n];
        ((float*)(g_img + OFF_TAIL + TAIL_B2))[n] = b2[n];
    }
}

// ============================ main fused kernel ============================
extern __shared__ char dynsmem[];

__global__ void __launch_bounds__(NTHREADS, 2)
enc_kernel(const int4* __restrict__ y4, float* __restrict__ out) {
    const int tid = threadIdx.x, wid = tid >> 5, lane = tid & 31;
    const int g = lane >> 2, tig = lane & 3;
    char* base = dynsmem;
    const uint32_t sb = smem_u32(base);
    const int nhalf = blockIdx.x & 1;              // which 128-col output half
    const int tilebase = (blockIdx.x >> 1) * TILE_M;

    // ---- stage weights: own w2 half + shared tail (overlaps with histogram) ----
    {
        const unsigned char* w2src = g_img + nhalf * W2H_BYTES;
        #pragma unroll 4
        for (int i = tid; i < W2H_BYTES / 16; i += NTHREADS)
            CP_ASYNC16(sb + S_W2 + i * 16, w2src + i * 16);
        const unsigned char* tsrc = g_img + OFF_TAIL;
        for (int i = tid; i < TAIL_BYTES / 16; i += NTHREADS)
            CP_ASYNC16(sb + S_W1 + i * 16, tsrc + i * 16);
        asm volatile("cp.async.commit_group;" ::: "memory");
    }

    // ---- per-task histogram + stats -> fp16 rows (48B stride, ldmatrix-friendly) ----
    for (int t = wid; t < TILE_M; t += NTHREADS / 32) {
        int4 v = y4[(size_t)(tilebase + t) * 32 + lane];   // 4 labels/lane, coalesced
        int hist[10];
        #pragma unroll
        for (int c = 0; c < 10; c++) {
            int cnt = (v.x == c) + (v.y == c) + (v.z == c) + (v.w == c);
            hist[c] = __reduce_add_sync(0xffffffffu, cnt);
        }
        if (lane == 0) {
            float pv[10], ent = 0.f, pmax = 0.f;
            int nnz = 0;
            #pragma unroll
            for (int c = 0; c < 10; c++) {
                float p = (float)hist[c] * 0.0078125f;     // /128 exact; exact in fp16
                pv[c] = p;
                ent -= p * __logf(p + 1e-6f);
                nnz += (hist[c] > 0);
                pmax = fmaxf(pmax, p);
            }
            __half2* st = (__half2*)(base + S_ST + t * ST_STRIDE);
            st[0] = __floats2half2_rn(pv[0], pv[1]);
            st[1] = __floats2half2_rn(pv[2], pv[3]);
            st[2] = __floats2half2_rn(pv[4], pv[5]);
            st[3] = __floats2half2_rn(pv[6], pv[7]);
            st[4] = __floats2half2_rn(pv[8], pv[9]);
            st[5] = __floats2half2_rn((float)nnz, ent);
            st[6] = __floats2half2_rn(0.0f, pmax);         // k=12 zeroed (folded into bias)
            st[7] = __floats2half2_rn(0.0f, 0.0f);         // K pad 14,15
        }
    }
    asm volatile("cp.async.wait_group 0;" ::: "memory");
    __syncthreads();

    const float* b1f = (const float*)(base + S_B1F);
    const float* b2s = (const float*)(base + S_B2);

    // ---- layer 1: h[16 rows/warp, 256] = stats @ w1 (K=16), GELU, keep as A-frags ----
    uint32_t h2[64];   // 16 k16-blocks x 4 b32 regs: A operand frags for layer 2
    {
        uint32_t sa = sb + S_ST + (uint32_t)(wid * 16 + (lane & 15)) * ST_STRIDE
                    + ((lane & 16) ? 16u : 0u);
        uint32_t a0, a1, a2, a3;
        LDSM_X4(a0, a1, a2, a3, sa);

        const uint32_t krow = (uint32_t)(lane & 15);
        #pragma unroll
        for (int np = 0; np < 16; np++) {
            const int n0 = np * 16;
            uint32_t baddr = sb + S_W1 + krow * W1_STRIDE
                           + ((uint32_t)n0 + ((lane & 16) ? 8u : 0u)) * 2u;
            uint32_t b0, b1_, b2_, b3;
            LDSM_X4_T(b0, b1_, b2_, b3, baddr);
            float c[8] = {0.f, 0.f, 0.f, 0.f, 0.f, 0.f, 0.f, 0.f};
            MMA16816(c + 0, a0, a1, a2, a3, b0, b1_);
            MMA16816(c + 4, a0, a1, a2, a3, b2_, b3);
            const int col0 = n0 + 2 * tig;
            float u0 = b1f[col0], u1 = b1f[col0 + 1];
            float u8 = b1f[col0 + 8], u9 = b1f[col0 + 9];
            __half2 p0 = __floats2half2_rn(fast_gelu(c[0] + u0), fast_gelu(c[1] + u1));
            __half2 p1 = __floats2half2_rn(fast_gelu(c[2] + u0), fast_gelu(c[3] + u1));
            __half2 p2 = __floats2half2_rn(fast_gelu(c[4] + u8), fast_gelu(c[5] + u9));
            __half2 p3 = __floats2half2_rn(fast_gelu(c[6] + u8), fast_gelu(c[7] + u9));
            h2[np * 4 + 0] = *(uint32_t*)&p0;
            h2[np * 4 + 1] = *(uint32_t*)&p1;
            h2[np * 4 + 2] = *(uint32_t*)&p2;
            h2[np * 4 + 3] = *(uint32_t*)&p3;
        }
    }

    // ---- layer 2: out[16 rows/warp, 128-col half] = h @ w2half (K=256) + b2 ----
    {
        const int row0 = tilebase + wid * 16 + g;
        const int colbase = nhalf * 128;
        #pragma unroll 4
        for (int nt = 0; nt < 16; nt++) {
            float c[4] = {0.f, 0.f, 0.f, 0.f};
            #pragma unroll
            for (int ks = 0; ks < 8; ks++) {
                // B frags: k = ks*32 .. +31 (lane-per-row), n = nt*8 .. +7 (local)
                uint32_t baddr = sb + S_W2
                               + (uint32_t)(ks * 32 + lane) * W2H_STRIDE + (uint32_t)nt * 16u;
                uint32_t b0, b1_, b2_, b3;
                LDSM_X4_T(b0, b1_, b2_, b3, baddr);
                MMA16816(c, h2[(2 * ks) * 4 + 0], h2[(2 * ks) * 4 + 1],
                            h2[(2 * ks) * 4 + 2], h2[(2 * ks) * 4 + 3], b0, b1_);
                MMA16816(c, h2[(2 * ks + 1) * 4 + 0], h2[(2 * ks + 1) * 4 + 1],
                            h2[(2 * ks + 1) * 4 + 2], h2[(2 * ks + 1) * 4 + 3], b2_, b3);
            }
            const int lcol = nt * 8 + 2 * tig;
            const int col0 = colbase + lcol;
            float2 v0, v1;
            v0.x = c[0] + b2s[col0];
            v0.y = c[1] + b2s[col0 + 1];
            v1.x = c[2] + b2s[col0];
            v1.y = c[3] + b2s[col0 + 1];
            *(float2*)(out + (size_t)row0 * TD + col0) = v0;
            *(float2*)(out + (size_t)(row0 + 8) * TD + col0) = v1;
        }
    }
}

// ============================ launch ============================
extern "C" void kernel_launch(void* const* d_in, const int* in_sizes, int n_in,
                              void* d_out, int out_size) {
    const int*   y  = (const int*)d_in[0];
    const float* w1 = (const float*)d_in[1];
    const float* b1 = (const float*)d_in[2];
    const float* w2 = (const float*)d_in[3];
    const float* b2 = (const float*)d_in[4];
    float* out = (float*)d_out;

    const int Btasks = in_sizes[0] / 128;          // S = 128
    const int ntiles = Btasks / TILE_M;            // 512 for B=65536

    prep_kernel<<<257, TD>>>(w1, b1, w2, b2);

    cudaFuncSetAttribute(enc_kernel, cudaFuncAttributeMaxDynamicSharedMemorySize, SMEM_DYN);
    enc_kernel<<<ntiles * 2, NTHREADS, SMEM_DYN>>>((const int4*)y, out);
}

// round 9
// speedup vs baseline: 1.1751x; 1.1751x over previous
#include <cuda_runtime.h>
#include <cuda_fp16.h>
#include <cstdint>

#define TD 256
#define TILE_M 128
#define NTHREADS 256

// ---- w2 quarter images: 256 k-rows x 144B (144=9*16: aligned + phase-conflict-free) ----
#define W2Q_STRIDE 144
#define W2Q_BYTES  (256 * W2Q_STRIDE)        // 36864 per quarter
#define W1_STRIDE  528
#define OFF_TAIL   (4 * W2Q_BYTES)           // 147456
#define TAIL_W1    0
#define TAIL_B1F   (16 * W1_STRIDE)          // 8448
#define TAIL_B2    (TAIL_B1F + 1024)         // 9472
#define TAIL_BYTES (TAIL_B2 + 1024)          // 10496
#define IMG_BYTES  (OFF_TAIL + TAIL_BYTES)

__device__ __align__(16) unsigned char g_img[IMG_BYTES];
// h activations in m16n8k16 A-fragment layout: [m16_tile][k16_block][lane] = uint4
// 65536/16 = 4096 m16-tiles x 16 k-blocks x 32 lanes x 16B = 32MB
__device__ uint4 g_hfrag[4096 * 16 * 32];

// ---- pass-1 smem ----
#define S1_W1   0
#define S1_B1F  (16 * W1_STRIDE)             // 8448
#define S1_ST   (S1_B1F + 1024)              // 9472
#define ST_STRIDE 48
#define SMEM_P1 (S1_ST + TILE_M * ST_STRIDE) // 15616

// ---- pass-2 smem ----
#define S2_W2   0
#define S2_B2   W2Q_BYTES                    // 36864
#define SMEM_P2 (S2_B2 + 1024)               // 37888

// ============================ helpers ============================
__device__ __forceinline__ uint32_t smem_u32(const void* p) {
    uint32_t a;
    asm("{ .reg .u64 t; cvta.to.shared.u64 t, %1; cvt.u32.u64 %0, t; }"
        : "=r"(a) : "l"(p));
    return a;
}

#define LDSM_X4(r0, r1, r2, r3, addr) \
    asm volatile("ldmatrix.sync.aligned.m8n8.x4.shared.b16 {%0,%1,%2,%3}, [%4];" \
        : "=r"(r0), "=r"(r1), "=r"(r2), "=r"(r3) : "r"(addr))

#define LDSM_X4_T(r0, r1, r2, r3, addr) \
    asm volatile("ldmatrix.sync.aligned.m8n8.x4.trans.shared.b16 {%0,%1,%2,%3}, [%4];" \
        : "=r"(r0), "=r"(r1), "=r"(r2), "=r"(r3) : "r"(addr))

// D += A @ B : m16n8k16, fp16 in, fp32 accumulate
#define MMA16816(c, a0, a1, a2, a3, b0, b1) \
    asm volatile("mma.sync.aligned.m16n8k16.row.col.f32.f16.f16.f32 " \
        "{%0,%1,%2,%3}, {%4,%5,%6,%7}, {%8,%9}, {%0,%1,%2,%3};" \
        : "+f"((c)[0]), "+f"((c)[1]), "+f"((c)[2]), "+f"((c)[3]) \
        : "r"(a0), "r"(a1), "r"(a2), "r"(a3), "r"(b0), "r"(b1))

#define CP_ASYNC16(dst, src) \
    asm volatile("cp.async.ca.shared.global [%0], [%1], 16;" \
        :: "r"(dst), "l"(src) : "memory")

__device__ __forceinline__ float fast_gelu(float x) {
    float t = 0.7978845608f * x * fmaf(0.044715f, x * x, 1.0f);
    float th;
    asm("tanh.approx.f32 %0, %1;" : "=f"(th) : "f"(t));
    return 0.5f * x * (1.0f + th);
}

// ============================ prep kernel ============================
// Blocks 0..255: w2 row k -> quarter images (n>>6 quarter, n&63 local col).
// Block 256: w1 (zero-padded k=16) + folded fp32 bias + b2 into tail.
__global__ void prep_kernel(const float* __restrict__ w1, const float* __restrict__ b1,
                            const float* __restrict__ w2, const float* __restrict__ b2) {
    const int n = threadIdx.x;
    const int blk = blockIdx.x;
    if (blk < 256) {
        *(__half*)(g_img + (n >> 6) * W2Q_BYTES + blk * W2Q_STRIDE + (n & 63) * 2)
            = __float2half_rn(w2[blk * TD + n]);
    } else {
        #pragma unroll
        for (int k = 0; k < 16; k++) {
            float v = (k < 14) ? w1[k * TD + n] : 0.0f;
            *(__half*)(g_img + OFF_TAIL + TAIL_W1 + k * W1_STRIDE + n * 2) = __float2half_rn(v);
        }
        ((float*)(g_img + OFF_TAIL + TAIL_B1F))[n] = b1[n] + 128.0f * w1[12 * TD + n];
        ((float*)(g_img + OFF_TAIL + TAIL_B2))[n] = b2[n];
    }
}

// ============================ pass 1: stats + layer1 + GELU ============================
extern __shared__ char dynsmem[];

__global__ void __launch_bounds__(NTHREADS, 4)
stats_kernel(const int4* __restrict__ y4) {
    const int tid = threadIdx.x, wid = tid >> 5, lane = tid & 31;
    const int tig = lane & 3;
    char* base = dynsmem;
    const uint32_t sb = smem_u32(base);
    const int tilebase = blockIdx.x * TILE_M;

    // stage w1 + b1f (overlaps with histogram)
    {
        const unsigned char* src = g_img + OFF_TAIL;
        for (int i = tid; i < (TAIL_B1F + 1024) / 16; i += NTHREADS)
            CP_ASYNC16(sb + i * 16, src + i * 16);
        asm volatile("cp.async.commit_group;" ::: "memory");
    }

    // ---- per-task histogram + stats -> fp16 rows (48B stride, ldmatrix-friendly) ----
    for (int t = wid; t < TILE_M; t += NTHREADS / 32) {
        int4 v = y4[(size_t)(tilebase + t) * 32 + lane];   // 4 labels/lane, coalesced
        int hist[10];
        #pragma unroll
        for (int c = 0; c < 10; c++) {
            int cnt = (v.x == c) + (v.y == c) + (v.z == c) + (v.w == c);
            hist[c] = __reduce_add_sync(0xffffffffu, cnt);
        }
        if (lane == 0) {
            float pv[10], ent = 0.f, pmax = 0.f;
            int nnz = 0;
            #pragma unroll
            for (int c = 0; c < 10; c++) {
                float p = (float)hist[c] * 0.0078125f;     // /128 exact; exact in fp16
                pv[c] = p;
                ent -= p * __logf(p + 1e-6f);
                nnz += (hist[c] > 0);
                pmax = fmaxf(pmax, p);
            }
            __half2* st = (__half2*)(base + S1_ST + t * ST_STRIDE);
            st[0] = __floats2half2_rn(pv[0], pv[1]);
            st[1] = __floats2half2_rn(pv[2], pv[3]);
            st[2] = __floats2half2_rn(pv[4], pv[5]);
            st[3] = __floats2half2_rn(pv[6], pv[7]);
            st[4] = __floats2half2_rn(pv[8], pv[9]);
            st[5] = __floats2half2_rn((float)nnz, ent);
            st[6] = __floats2half2_rn(0.0f, pmax);         // k=12 zeroed (folded into bias)
            st[7] = __floats2half2_rn(0.0f, 0.0f);         // K pad 14,15
        }
    }
    asm volatile("cp.async.wait_group 0;" ::: "memory");
    __syncthreads();

    const float* b1f = (const float*)(base + S1_B1F);

    // ---- layer 1: h[16 rows/warp, 256] = stats @ w1 (K=16), GELU -> A-frags to gmem ----
    {
        uint32_t sa = sb + S1_ST + (uint32_t)(wid * 16 + (lane & 15)) * ST_STRIDE
                    + ((lane & 16) ? 16u : 0u);
        uint32_t a0, a1, a2, a3;
        LDSM_X4(a0, a1, a2, a3, sa);

        const int m16 = blockIdx.x * 8 + wid;              // global m16-tile index
        uint4* hdst = g_hfrag + ((size_t)m16 * 16) * 32 + lane;
        const uint32_t krow = (uint32_t)(lane & 15);
        #pragma unroll
        for (int np = 0; np < 16; np++) {
            const int n0 = np * 16;
            uint32_t baddr = sb + S1_W1 + krow * W1_STRIDE
                           + ((uint32_t)n0 + ((lane & 16) ? 8u : 0u)) * 2u;
            uint32_t b0, b1_, b2_, b3;
            LDSM_X4_T(b0, b1_, b2_, b3, baddr);
            float c[8] = {0.f, 0.f, 0.f, 0.f, 0.f, 0.f, 0.f, 0.f};
            MMA16816(c + 0, a0, a1, a2, a3, b0, b1_);
            MMA16816(c + 4, a0, a1, a2, a3, b2_, b3);
            const int col0 = n0 + 2 * tig;
            float u0 = b1f[col0], u1 = b1f[col0 + 1];
            float u8 = b1f[col0 + 8], u9 = b1f[col0 + 9];
            __half2 p0 = __floats2half2_rn(fast_gelu(c[0] + u0), fast_gelu(c[1] + u1));
            __half2 p1 = __floats2half2_rn(fast_gelu(c[2] + u0), fast_gelu(c[3] + u1));
            __half2 p2 = __floats2half2_rn(fast_gelu(c[4] + u8), fast_gelu(c[5] + u9));
            __half2 p3 = __floats2half2_rn(fast_gelu(c[6] + u8), fast_gelu(c[7] + u9));
            uint4 v;
            v.x = *(uint32_t*)&p0;   // rows g,   k 2tig,2tig+1
            v.y = *(uint32_t*)&p1;   // rows g+8
            v.z = *(uint32_t*)&p2;   // rows g,   k +8
            v.w = *(uint32_t*)&p3;   // rows g+8, k +8
            hdst[np * 32] = v;       // coalesced 512B per warp-store
        }
    }
}

// ============================ pass 2: pure GEMM ============================
__global__ void __launch_bounds__(NTHREADS, 2)
gemm_kernel(float* __restrict__ out) {
    const int tid = threadIdx.x, wid = tid >> 5, lane = tid & 31;
    const int g = lane >> 2, tig = lane & 3;
    char* base = dynsmem;
    const uint32_t sb = smem_u32(base);
    const int q = blockIdx.x & 3;                  // output column quarter (64 cols)
    const int mtile = blockIdx.x >> 2;

    // stage w2 quarter + b2 (async)
    {
        const unsigned char* w2src = g_img + q * W2Q_BYTES;
        #pragma unroll 4
        for (int i = tid; i < W2Q_BYTES / 16; i += NTHREADS)
            CP_ASYNC16(sb + S2_W2 + i * 16, w2src + i * 16);
        if (tid < 64)
            CP_ASYNC16(sb + S2_B2 + tid * 16, g_img + OFF_TAIL + TAIL_B2 + tid * 16);
        asm volatile("cp.async.commit_group;" ::: "memory");
    }

    // A-fragments via plain ldg.v4 (latency hides under cp.async staging)
    const int m16 = mtile * 8 + wid;
    uint4 a[16];
    {
        const uint4* hsrc = g_hfrag + ((size_t)m16 * 16) * 32 + lane;
        #pragma unroll
        for (int np = 0; np < 16; np++) a[np] = hsrc[np * 32];
    }

    asm volatile("cp.async.wait_group 0;" ::: "memory");
    __syncthreads();

    const float* b2s = (const float*)(base + S2_B2);
    const int row0 = mtile * TILE_M + wid * 16 + g;
    const int colbase = q * 64;

    #pragma unroll 2
    for (int nt = 0; nt < 8; nt++) {
        float c[4] = {0.f, 0.f, 0.f, 0.f};
        #pragma unroll
        for (int ks = 0; ks < 8; ks++) {
            // B frags: k = ks*32 .. +31 (lane-per-row), n = nt*8 .. +7 (local)
            uint32_t baddr = sb + S2_W2
                           + (uint32_t)(ks * 32 + lane) * W2Q_STRIDE + (uint32_t)nt * 16u;
            uint32_t b0, b1_, b2_, b3;
            LDSM_X4_T(b0, b1_, b2_, b3, baddr);
            MMA16816(c, a[2 * ks].x, a[2 * ks].y, a[2 * ks].z, a[2 * ks].w, b0, b1_);
            MMA16816(c, a[2 * ks + 1].x, a[2 * ks + 1].y,
                        a[2 * ks + 1].z, a[2 * ks + 1].w, b2_, b3);
        }
        const int lcol = nt * 8 + 2 * tig;
        const int col0 = colbase + lcol;
        float2 v0, v1;
        v0.x = c[0] + b2s[col0];
        v0.y = c[1] + b2s[col0 + 1];
        v1.x = c[2] + b2s[col0];
        v1.y = c[3] + b2s[col0 + 1];
        *(float2*)(out + (size_t)row0 * TD + col0) = v0;
        *(float2*)(out + (size_t)(row0 + 8) * TD + col0) = v1;
    }
}

// ============================ launch ============================
extern "C" void kernel_launch(void* const* d_in, const int* in_sizes, int n_in,
                              void* d_out, int out_size) {
    const int*   y  = (const int*)d_in[0];
    const float* w1 = (const float*)d_in[1];
    const float* b1 = (const float*)d_in[2];
    const float* w2 = (const float*)d_in[3];
    const float* b2 = (const float*)d_in[4];
    float* out = (float*)d_out;

    const int Btasks = in_sizes[0] / 128;          // S = 128
    const int ntiles = Btasks / TILE_M;            // 512 for B=65536

    prep_kernel<<<257, TD>>>(w1, b1, w2, b2);

    cudaFuncSetAttribute(stats_kernel, cudaFuncAttributeMaxDynamicSharedMemorySize, SMEM_P1);
    stats_kernel<<<ntiles, NTHREADS, SMEM_P1>>>((const int4*)y);

    cudaFuncSetAttribute(gemm_kernel, cudaFuncAttributeMaxDynamicSharedMemorySize, SMEM_P2);
    gemm_kernel<<<ntiles * 4, NTHREADS, SMEM_P2>>>(out);
}